// round 12
// baseline (speedup 1.0000x reference)
#include <cuda_runtime.h>
#include <math.h>

typedef unsigned long long u64;

#define T_    2048
#define NB_   64
#define NU_   8
#define NH_   256
#define H2_   128
#define NY_   8
#define S_    32           // k_main segments (L_=64 each)
#define L_    64
#define LSEG_ 16           // virtual (chain) segment length
#define NV_   128          // virtual segments = T_/LSEG_
#define NSQ_  4            // log2(LSEG_)
#define NBP_  32           // NB_/2 (batch pairs)
#define CH_   16           // chunk rows in k_main
#define NCH_  4            // chunks per k_main block (4 steps x 4 chains each)
#define XROW_ 256          // Xs row stride (u64); all accesses lane-contiguous

// scratch (device globals; no allocation allowed)
__device__ u64 g_final[NV_][NBP_][H2_][2];
__device__ u64 g_init [NV_][NBP_][H2_][2];

// precomputed constants (k_pre)
__device__ float2 g_lam [H2_];     // lambda
__device__ float2 g_lamL[H2_];     // lambda^LSEG
__device__ __align__(16) u64 g_B1p[H2_][NU_];  // splat(B[h]*exp(mB[h]))
__device__ __align__(16) u64 g_B2p[H2_][NU_];  // splat(B[h+H2]*exp(mB[h+H2]))

// ---- packed f32x2 helpers (Blackwell FFMA2 path) ----
static __device__ __forceinline__ u64 pk2(float lo, float hi) {
    u64 r; asm("mov.b64 %0, {%1,%2};" : "=l"(r) : "f"(lo), "f"(hi)); return r;
}
static __device__ __forceinline__ void upk2(u64 v, float& lo, float& hi) {
    asm("mov.b64 {%0,%1}, %2;" : "=f"(lo), "=f"(hi) : "l"(v));
}
static __device__ __forceinline__ u64 ffma2(u64 a, u64 b, u64 c) {
    u64 d; asm("fma.rn.f32x2 %0,%1,%2,%3;" : "=l"(d) : "l"(a), "l"(b), "l"(c)); return d;
}
static __device__ __forceinline__ u64 fmul2(u64 a, u64 b) {
    u64 d; asm("mul.rn.f32x2 %0,%1,%2;" : "=l"(d) : "l"(a), "l"(b)); return d;
}
static __device__ __forceinline__ u64 fadd2(u64 a, u64 b) {
    u64 d; asm("add.rn.f32x2 %0,%1,%2;" : "=l"(d) : "l"(a), "l"(b)); return d;
}
static __device__ __forceinline__ u64 splat(float v) { return pk2(v, v); }

static __device__ __forceinline__ void load_B_splats(int h, u64* Bp1, u64* Bp2) {
    const ulonglong2* p1 = (const ulonglong2*)g_B1p[h];
    const ulonglong2* p2 = (const ulonglong2*)g_B2p[h];
    ulonglong2 a0 = p1[0], a1 = p1[1], a2 = p1[2], a3 = p1[3];
    ulonglong2 c0 = p2[0], c1 = p2[1], c2 = p2[2], c3 = p2[3];
    Bp1[0]=a0.x; Bp1[1]=a0.y; Bp1[2]=a1.x; Bp1[3]=a1.y;
    Bp1[4]=a2.x; Bp1[5]=a2.y; Bp1[6]=a3.x; Bp1[7]=a3.y;
    Bp2[0]=c0.x; Bp2[1]=c0.y; Bp2[2]=c1.x; Bp2[3]=c1.y;
    Bp2[4]=c2.x; Bp2[5]=c2.y; Bp2[6]=c3.x; Bp2[7]=c3.y;
}

// =====================================================================
// Kernel 0: one-time constant precompute (all DP math lives here)
// grid 8 x 16 threads
// =====================================================================
__global__ void k_pre(
    const float* __restrict__ lr, const float* __restrict__ li,
    const float* __restrict__ B, const float* __restrict__ mB)
{
    const int h = blockIdx.x * 16 + threadIdx.x;
    double e1 = exp((double)mB[h]);
    double e2 = exp((double)mB[h + H2_]);
    double r  = exp(-fabs((double)lr[h]));
    double th = 1.5707963267948966 * (double)li[h];
    double re = r * cos(th);
    double im = r * sin(th);
    g_lam[h]  = make_float2((float)re, (float)im);
    double pr = re, pi = im;
#pragma unroll
    for (int i = 0; i < NSQ_; ++i) {
        double nr = pr * pr - pi * pi;
        double ni = 2.0 * pr * pi;
        pr = nr; pi = ni;
    }
    g_lamL[h] = make_float2((float)pr, (float)pi);
#pragma unroll
    for (int u = 0; u < NU_; ++u) {
        float b1f = (float)((double)B[h * NU_ + u] * e1);
        float b2f = (float)((double)B[(h + H2_) * NU_ + u] * e2);
        g_B1p[h][u] = pk2(b1f, b1f);
        g_B2p[h][u] = pk2(b2f, b2f);
    }
}

// =====================================================================
// Kernel 1: per-block 64 t = 4 INDEPENDENT chains of 16 (zero init)
// grid (NBP_, S_), 128 threads; 4-way ILP on the serial rotation
// =====================================================================
__global__ void __launch_bounds__(128, 7) k_seg(const float* __restrict__ U)
{
    const int h  = threadIdx.x;
    const int bp = blockIdx.x;
    const int s  = blockIdx.y;
    const int b0 = bp << 1;

    u64 Bp1[NU_], Bp2[NU_];
    load_B_splats(h, Bp1, Bp2);
    float2 lm = g_lam[h];
    u64 re2 = splat(lm.x), im2 = splat(lm.y), ni2 = splat(-lm.y);

    // stage ALL 64 timesteps of U for this (s, bp): 4KB
    __shared__ __align__(16) u64 Us[L_][NU_];
    const float* Ub = U + ((size_t)s * L_ * NB_ + b0) * NU_;
#pragma unroll
    for (int k = 0; k < 4; ++k) {
        int idx = k * 128 + h;
        int t = idx >> 3, u = idx & 7;
        const float* p = Ub + (size_t)t * (NB_ * NU_) + u;
        Us[t][u] = pk2(p[0], p[NU_]);
    }
    __syncthreads();

    u64 x1[4] = {0,0,0,0}, x2[4] = {0,0,0,0};

#pragma unroll 2
    for (int i = 0; i < LSEG_; ++i) {
#pragma unroll
        for (int ch = 0; ch < 4; ++ch) {
            const int t = ch * LSEG_ + i;
            const ulonglong2* up = (const ulonglong2*)(&Us[t][0]);
            ulonglong2 ua = up[0], ub = up[1], uc = up[2], ud = up[3];
            u64 uu[8] = { ua.x, ua.y, ub.x, ub.y, uc.x, uc.y, ud.x, ud.y };
            u64 bu1 = fmul2(Bp1[0], uu[0]);
            u64 bu2 = fmul2(Bp2[0], uu[0]);
#pragma unroll
            for (int u = 1; u < NU_; ++u) {
                bu1 = ffma2(Bp1[u], uu[u], bu1);
                bu2 = ffma2(Bp2[u], uu[u], bu2);
            }
            u64 nx1 = ffma2(re2, x1[ch], ffma2(ni2, x2[ch], bu1));
            u64 nx2 = ffma2(re2, x2[ch], ffma2(im2, x1[ch], bu2));
            x1[ch] = nx1; x2[ch] = nx2;
        }
    }
#pragma unroll
    for (int ch = 0; ch < 4; ++ch) {
        const int v = s * 4 + ch;
        g_final[v][bp][h][0] = x1[ch];
        g_final[v][bp][h][1] = x2[ch];
    }
}

// =====================================================================
// Kernel 2: sequential combine across 128 virtual segments -> g_init
// grid (NBP_), 128 threads
// =====================================================================
__global__ void __launch_bounds__(128, 1) k_comb(
    const float* __restrict__ y0,
    const float* __restrict__ Wyx, const float* __restrict__ byx)
{
    const int h  = threadIdx.x;
    const int bp = blockIdx.x;
    const int b0 = bp << 1;

    float2 lL = g_lamL[h];
    u64 pr2 = splat(lL.x), pi2 = splat(lL.y), npi2 = splat(-lL.y);

    // x0 = y0 @ Wy2x^T + by2x (batch-pair packed)
    u64 z1 = splat(byx[h]), z2 = splat(byx[h + H2_]);
#pragma unroll
    for (int y = 0; y < NY_; ++y) {
        u64 yv = pk2(y0[b0 * NY_ + y], y0[(b0 + 1) * NY_ + y]);
        z1 = ffma2(splat(Wyx[h * NY_ + y]), yv, z1);
        z2 = ffma2(splat(Wyx[(h + H2_) * NY_ + y]), yv, z2);
    }
#pragma unroll 4
    for (int v = 0; v < NV_; ++v) {
        g_init[v][bp][h][0] = z1;
        g_init[v][bp][h][1] = z2;
        u64 f1 = g_final[v][bp][h][0];
        u64 f2 = g_final[v][bp][h][1];
        u64 n1 = ffma2(pr2, z1, ffma2(npi2, z2, f1));
        u64 n2 = ffma2(pr2, z2, ffma2(pi2,  z1, f2));
        z1 = n1; z2 = n2;
    }
}

// =====================================================================
// Kernel 3: re-scan (4 chains interleaved) + fused Y projection
// grid (NBP_, S_), 128 threads, dynamic shared
// shared (u64): Xs[CH_][XROW_] | WkT[NY_][NH_] | Us[CH_][NU_]  (~49KB)
// chunk c rows: r = ch*4 + i  <->  t_seg = ch*16 + c*4 + i
// Phase B (R9): warp tg -> rows tg*4..+3; lane k-strided by 32; butterfly
// =====================================================================
#define SM3_U64 (CH_ * XROW_ + NY_ * NH_ + CH_ * NU_)
#define SM3_BYTES (SM3_U64 * 8)

__global__ void __launch_bounds__(128, 4) k_main(
    const float* __restrict__ U,
    const float* __restrict__ Wxy, const float* __restrict__ bxy,
    float* __restrict__ Y)
{
    extern __shared__ __align__(16) u64 sm[];
    u64* Xs  = sm;                        // [CH_][XROW_], col k: 2h->x1, 2h+1->x2
    u64* WkT = sm + CH_ * XROW_;          // [NY_][NH_] transposed splats
    u64* Us  = WkT + NY_ * NH_;           // [CH_][NU_]

    const int tid = threadIdx.x;
    const int h   = tid;
    const int bp  = blockIdx.x;
    const int s   = blockIdx.y;
    const int b0  = bp << 1;

    // prepack W transposed: WkT[y][k] = splat(Wxy[y][colmap(k)])
#pragma unroll
    for (int i = 0; i < 16; ++i) {
        int idx = tid * 16 + i;          // 0..2047
        int y = idx >> 8, k = idx & 255;
        int hh = k >> 1;
        int col = (k & 1) ? (hh + H2_) : hh;
        WkT[y * NH_ + k] = splat(Wxy[y * NH_ + col]);
    }

    float2 lm = g_lam[h];
    u64 re2 = splat(lm.x), im2 = splat(lm.y), ni2 = splat(-lm.y);

    // 4 chain states from virtual-segment inits
    u64 x1[4], x2[4];
#pragma unroll
    for (int ch = 0; ch < 4; ++ch) {
        const int v = s * 4 + ch;
        x1[ch] = g_init[v][bp][h][0];
        x2[ch] = g_init[v][bp][h][1];
    }

    // phase-B roles (R9)
    const int lane = tid & 31;
    const int tg   = tid >> 5;           // warp -> rows tg*4..tg*4+3 (chain tg)
    const int t_local = lane >> 3;       // owned row-within-quad after allreduce
    const int oy      = lane & 7;
    const u64 biasp = splat(bxy[oy]);

    const float* Ub = U + ((size_t)s * L_ * NB_ + b0) * NU_;

    for (int c = 0; c < NCH_; ++c) {
        __syncthreads();                 // prev-chunk Xs reads done before rewrite
        {   // stage U for this chunk's 16 scattered rows
            int r = tid >> 3, u = tid & 7;
            int t_seg = (r >> 2) * LSEG_ + c * 4 + (r & 3);
            const float* p = Ub + (size_t)t_seg * (NB_ * NU_) + u;
            Us[r * NU_ + u] = pk2(p[0], p[NU_]);
        }
        __syncthreads();

        // reload B splats per chunk (dead during phase B -> lower live regs)
        u64 Bp1[NU_], Bp2[NU_];
        load_B_splats(h, Bp1, Bp2);

        // ---- phase A: 4 steps on each of 4 independent chains ----
#pragma unroll
        for (int i = 0; i < 4; ++i) {
#pragma unroll
            for (int ch = 0; ch < 4; ++ch) {
                const int r = ch * 4 + i;
                const ulonglong2* up = (const ulonglong2*)(Us + r * NU_);
                ulonglong2 ua = up[0], ub = up[1], uc = up[2], ud = up[3];
                u64 uu[8] = { ua.x, ua.y, ub.x, ub.y, uc.x, uc.y, ud.x, ud.y };
                u64 bu1 = fmul2(Bp1[0], uu[0]);
                u64 bu2 = fmul2(Bp2[0], uu[0]);
#pragma unroll
                for (int u = 1; u < NU_; ++u) {
                    bu1 = ffma2(Bp1[u], uu[u], bu1);
                    bu2 = ffma2(Bp2[u], uu[u], bu2);
                }
                u64 nx1 = ffma2(re2, x1[ch], ffma2(ni2, x2[ch], bu1));
                u64 nx2 = ffma2(re2, x2[ch], ffma2(im2, x1[ch], bu2));
                x1[ch] = nx1; x2[ch] = nx2;
                *((ulonglong2*)(Xs + (size_t)r * XROW_ + 2 * h)) =
                    make_ulonglong2(nx1, nx2);
            }
        }
        __syncthreads();

        // ---- phase B: Y GEMM (R9 mapping) ----
        u64 acc[32];
#pragma unroll
        for (int v = 0; v < 32; ++v) acc[v] = 0ull;

        const u64* xb0 = Xs + (size_t)(tg * 4 + 0) * XROW_ + lane;
        const u64* xb1 = Xs + (size_t)(tg * 4 + 1) * XROW_ + lane;
        const u64* xb2 = Xs + (size_t)(tg * 4 + 2) * XROW_ + lane;
        const u64* xb3 = Xs + (size_t)(tg * 4 + 3) * XROW_ + lane;
        const u64* wb  = WkT + lane;

#pragma unroll
        for (int j = 0; j < 8; ++j) {
            const int ko = j * 32;
            u64 xv0 = xb0[ko], xv1 = xb1[ko], xv2 = xb2[ko], xv3 = xb3[ko];
            u64 w0 = wb[0 * NH_ + ko], w1 = wb[1 * NH_ + ko];
            u64 w2 = wb[2 * NH_ + ko], w3 = wb[3 * NH_ + ko];
            u64 w4 = wb[4 * NH_ + ko], w5 = wb[5 * NH_ + ko];
            u64 w6 = wb[6 * NH_ + ko], w7 = wb[7 * NH_ + ko];

            acc[ 0] = ffma2(w0, xv0, acc[ 0]); acc[ 1] = ffma2(w1, xv0, acc[ 1]);
            acc[ 2] = ffma2(w2, xv0, acc[ 2]); acc[ 3] = ffma2(w3, xv0, acc[ 3]);
            acc[ 4] = ffma2(w4, xv0, acc[ 4]); acc[ 5] = ffma2(w5, xv0, acc[ 5]);
            acc[ 6] = ffma2(w6, xv0, acc[ 6]); acc[ 7] = ffma2(w7, xv0, acc[ 7]);
            acc[ 8] = ffma2(w0, xv1, acc[ 8]); acc[ 9] = ffma2(w1, xv1, acc[ 9]);
            acc[10] = ffma2(w2, xv1, acc[10]); acc[11] = ffma2(w3, xv1, acc[11]);
            acc[12] = ffma2(w4, xv1, acc[12]); acc[13] = ffma2(w5, xv1, acc[13]);
            acc[14] = ffma2(w6, xv1, acc[14]); acc[15] = ffma2(w7, xv1, acc[15]);
            acc[16] = ffma2(w0, xv2, acc[16]); acc[17] = ffma2(w1, xv2, acc[17]);
            acc[18] = ffma2(w2, xv2, acc[18]); acc[19] = ffma2(w3, xv2, acc[19]);
            acc[20] = ffma2(w4, xv2, acc[20]); acc[21] = ffma2(w5, xv2, acc[21]);
            acc[22] = ffma2(w6, xv2, acc[22]); acc[23] = ffma2(w7, xv2, acc[23]);
            acc[24] = ffma2(w0, xv3, acc[24]); acc[25] = ffma2(w1, xv3, acc[25]);
            acc[26] = ffma2(w2, xv3, acc[26]); acc[27] = ffma2(w3, xv3, acc[27]);
            acc[28] = ffma2(w4, xv3, acc[28]); acc[29] = ffma2(w5, xv3, acc[29]);
            acc[30] = ffma2(w6, xv3, acc[30]); acc[31] = ffma2(w7, xv3, acc[31]);
        }

        // ---- butterfly allreduce over 32 lanes with value exchange ----
        {
            int n = 32;
#pragma unroll
            for (int d = 16; d >= 1; d >>= 1) {
                n >>= 1;
                const bool hi = (lane & d) != 0;
#pragma unroll
                for (int i = 0; i < 16; ++i) {
                    if (i < n) {
                        u64 snd = hi ? acc[i] : acc[i + n];
                        u64 rcv = __shfl_xor_sync(0xFFFFFFFFu, snd, d);
                        u64 kp  = hi ? acc[i + n] : acc[i];
                        acc[i] = fadd2(kp, rcv);
                    }
                }
            }
        }

        // lane owns (row tg*4 + t_local, oy); add bias, store straight to Y
        {
            u64 r = fadd2(acc[0], biasp);
            float f0, f1; upk2(r, f0, f1);
            int tgl = s * L_ + tg * LSEG_ + c * 4 + t_local;
            float* yp = Y + ((size_t)tgl * NB_ + b0) * NY_ + oy;
            yp[0]   = f0;
            yp[NY_] = f1;
        }
    }
}

// =====================================================================
extern "C" void kernel_launch(void* const* d_in, const int* in_sizes, int n_in,
                              void* d_out, int out_size)
{
    const float* y0  = (const float*)d_in[0];
    const float* U   = (const float*)d_in[1];
    const float* lr  = (const float*)d_in[2];
    const float* li  = (const float*)d_in[3];
    const float* B   = (const float*)d_in[4];
    const float* mB  = (const float*)d_in[5];
    const float* Wyx = (const float*)d_in[6];
    const float* byx = (const float*)d_in[7];
    const float* Wxy = (const float*)d_in[8];
    const float* bxy = (const float*)d_in[9];
    float* Y = (float*)d_out;

    cudaFuncSetAttribute(k_main, cudaFuncAttributeMaxDynamicSharedMemorySize, SM3_BYTES);

    dim3 grid(NBP_, S_);
    k_pre <<<8, 16>>>(lr, li, B, mB);
    k_seg <<<grid, 128>>>(U);
    k_comb<<<NBP_, 128>>>(y0, Wyx, byx);
    k_main<<<grid, 128, SM3_BYTES>>>(U, Wxy, bxy, Y);
}

// round 13
// speedup vs baseline: 1.1456x; 1.1456x over previous
#include <cuda_runtime.h>
#include <math.h>

typedef unsigned long long u64;

#define T_    2048
#define NB_   64
#define NU_   8
#define NH_   256
#define H2_   128
#define NY_   8
#define S_    32           // blocks along T (64 t each)
#define L_    64
#define LSEG_ 32           // chain length (2 chains per block)
#define NV_   64           // virtual segments = T_/LSEG_
#define NSQ_  5            // log2(LSEG_)
#define NBP_  32           // NB_/2 (batch pairs)
#define CH_   16           // chunk rows in k_main (2 chains x 8 steps)
#define NCH_  4
#define XROW_ 256          // Xs row stride (u64)

// scratch (device globals; no allocation allowed)
__device__ u64 g_final[NV_][NBP_][H2_][2];
__device__ u64 g_init [NV_][NBP_][H2_][2];

// precomputed constants (k_pre)
__device__ float2 g_lam [H2_];     // lambda
__device__ float2 g_lam2[H2_];     // lambda^2
__device__ float2 g_lamL[H2_];     // lambda^LSEG
__device__ float  g_B1[H2_][NU_];  // B[h]   * exp(mB[h])
__device__ float  g_B2[H2_][NU_];  // B[h+H2]* exp(mB[h+H2])
__device__ float  g_C1[H2_][NU_];  // re*B1 - im*B2
__device__ float  g_C2[H2_][NU_];  // im*B1 + re*B2
__device__ __align__(16) u64 g_B1p[H2_][NU_];
__device__ __align__(16) u64 g_B2p[H2_][NU_];

// ---- packed f32x2 helpers ----
static __device__ __forceinline__ u64 pk2(float lo, float hi) {
    u64 r; asm("mov.b64 %0, {%1,%2};" : "=l"(r) : "f"(lo), "f"(hi)); return r;
}
static __device__ __forceinline__ void upk2(u64 v, float& lo, float& hi) {
    asm("mov.b64 {%0,%1}, %2;" : "=f"(lo), "=f"(hi) : "l"(v));
}
static __device__ __forceinline__ u64 ffma2(u64 a, u64 b, u64 c) {
    u64 d; asm("fma.rn.f32x2 %0,%1,%2,%3;" : "=l"(d) : "l"(a), "l"(b), "l"(c)); return d;
}
static __device__ __forceinline__ u64 fmul2(u64 a, u64 b) {
    u64 d; asm("mul.rn.f32x2 %0,%1,%2;" : "=l"(d) : "l"(a), "l"(b)); return d;
}
static __device__ __forceinline__ u64 fadd2(u64 a, u64 b) {
    u64 d; asm("add.rn.f32x2 %0,%1,%2;" : "=l"(d) : "l"(a), "l"(b)); return d;
}
static __device__ __forceinline__ u64 splat(float v) { return pk2(v, v); }

static __device__ __forceinline__ void load_B_splats(int h, u64* Bp1, u64* Bp2) {
    const ulonglong2* p1 = (const ulonglong2*)g_B1p[h];
    const ulonglong2* p2 = (const ulonglong2*)g_B2p[h];
    ulonglong2 a0 = p1[0], a1 = p1[1], a2 = p1[2], a3 = p1[3];
    ulonglong2 c0 = p2[0], c1 = p2[1], c2 = p2[2], c3 = p2[3];
    Bp1[0]=a0.x; Bp1[1]=a0.y; Bp1[2]=a1.x; Bp1[3]=a1.y;
    Bp1[4]=a2.x; Bp1[5]=a2.y; Bp1[6]=a3.x; Bp1[7]=a3.y;
    Bp2[0]=c0.x; Bp2[1]=c0.y; Bp2[2]=c1.x; Bp2[3]=c1.y;
    Bp2[4]=c2.x; Bp2[5]=c2.y; Bp2[6]=c3.x; Bp2[7]=c3.y;
}

// =====================================================================
// Kernel 0: one-time constant precompute (all DP math lives here)
// grid 8 x 16 threads
// =====================================================================
__global__ void k_pre(
    const float* __restrict__ lr, const float* __restrict__ li,
    const float* __restrict__ B, const float* __restrict__ mB)
{
    const int h = blockIdx.x * 16 + threadIdx.x;
    double e1 = exp((double)mB[h]);
    double e2 = exp((double)mB[h + H2_]);
    double r  = exp(-fabs((double)lr[h]));
    double th = 1.5707963267948966 * (double)li[h];
    double re = r * cos(th);
    double im = r * sin(th);
    g_lam[h]  = make_float2((float)re, (float)im);
    g_lam2[h] = make_float2((float)(re * re - im * im), (float)(2.0 * re * im));
    double pr = re, pi = im;
#pragma unroll
    for (int i = 0; i < NSQ_; ++i) {
        double nr = pr * pr - pi * pi;
        double ni = 2.0 * pr * pi;
        pr = nr; pi = ni;
    }
    g_lamL[h] = make_float2((float)pr, (float)pi);
#pragma unroll
    for (int u = 0; u < NU_; ++u) {
        double b1 = (double)B[h * NU_ + u] * e1;
        double b2 = (double)B[(h + H2_) * NU_ + u] * e2;
        float b1f = (float)b1, b2f = (float)b2;
        g_B1[h][u] = b1f;
        g_B2[h][u] = b2f;
        g_B1p[h][u] = pk2(b1f, b1f);
        g_B2p[h][u] = pk2(b2f, b2f);
        g_C1[h][u] = (float)(re * b1 - im * b2);
        g_C2[h][u] = (float)(im * b1 + re * b2);
    }
}

// =====================================================================
// Kernel 1: per-block 64 t = 2 INDEPENDENT chains of 32, each with
// 2-step lambda^2 fusion -> 16 fused iterations, 2-way chain ILP.
// grid (NBP_, S_), 128 threads
// =====================================================================
__global__ void __launch_bounds__(128, 4) k_seg(const float* __restrict__ U)
{
    const int h  = threadIdx.x;
    const int bp = blockIdx.x;
    const int s  = blockIdx.y;
    const int b0 = bp << 1;

    u64 B1s[NU_], B2s[NU_], C1s[NU_], C2s[NU_];
#pragma unroll
    for (int u = 0; u < NU_; ++u) {
        B1s[u] = splat(g_B1[h][u]);
        B2s[u] = splat(g_B2[h][u]);
        C1s[u] = splat(g_C1[h][u]);
        C2s[u] = splat(g_C2[h][u]);
    }
    float2 l2 = g_lam2[h];
    u64 R2 = splat(l2.x), I2 = splat(l2.y), nI2 = splat(-l2.y);

    // stage ALL 64 timesteps of U for this (s, bp): 4KB, coalesced
    __shared__ __align__(16) u64 Us[L_][NU_];
    const float* Ub = U + ((size_t)s * L_ * NB_ + b0) * NU_;
#pragma unroll
    for (int k = 0; k < 4; ++k) {
        int idx = k * 128 + h;
        int t = idx >> 3, u = idx & 7;
        const float* p = Ub + (size_t)t * (NB_ * NU_) + u;
        Us[t][u] = pk2(p[0], p[NU_]);
    }
    __syncthreads();

    u64 x1[2] = {0, 0}, x2[2] = {0, 0};

#pragma unroll 2
    for (int i = 0; i < LSEG_ / 2; ++i) {
#pragma unroll
        for (int ch = 0; ch < 2; ++ch) {
            const int tA = ch * LSEG_ + 2 * i;
            const ulonglong2* pa = (const ulonglong2*)(&Us[tA][0]);
            ulonglong2 a0 = pa[0], a1 = pa[1], a2 = pa[2], a3 = pa[3];
            const ulonglong2* pb = (const ulonglong2*)(&Us[tA + 1][0]);
            ulonglong2 bq0 = pb[0], bq1 = pb[1], bq2 = pb[2], bq3 = pb[3];
            u64 uA[8] = { a0.x, a0.y, a1.x, a1.y, a2.x, a2.y, a3.x, a3.y };
            u64 uB[8] = { bq0.x, bq0.y, bq1.x, bq1.y, bq2.x, bq2.y, bq3.x, bq3.y };

            u64 p1 = fmul2(C1s[0], uA[0]);
            u64 q1 = fmul2(B1s[0], uB[0]);
            u64 p2 = fmul2(C2s[0], uA[0]);
            u64 q2 = fmul2(B2s[0], uB[0]);
#pragma unroll
            for (int u = 1; u < NU_; ++u) {
                p1 = ffma2(C1s[u], uA[u], p1);
                q1 = ffma2(B1s[u], uB[u], q1);
                p2 = ffma2(C2s[u], uA[u], p2);
                q2 = ffma2(B2s[u], uB[u], q2);
            }
            u64 acc1 = fadd2(p1, q1);
            u64 acc2 = fadd2(p2, q2);

            u64 nx1 = ffma2(R2, x1[ch], ffma2(nI2, x2[ch], acc1));
            u64 nx2 = ffma2(I2, x1[ch], ffma2(R2, x2[ch], acc2));
            x1[ch] = nx1; x2[ch] = nx2;
        }
    }
#pragma unroll
    for (int ch = 0; ch < 2; ++ch) {
        const int v = s * 2 + ch;
        g_final[v][bp][h][0] = x1[ch];
        g_final[v][bp][h][1] = x2[ch];
    }
}

// =====================================================================
// Kernel 2: sequential combine across 64 virtual segments -> g_init
// grid (NBP_), 128 threads
// =====================================================================
__global__ void __launch_bounds__(128, 1) k_comb(
    const float* __restrict__ y0,
    const float* __restrict__ Wyx, const float* __restrict__ byx)
{
    const int h  = threadIdx.x;
    const int bp = blockIdx.x;
    const int b0 = bp << 1;

    float2 lL = g_lamL[h];
    u64 pr2 = splat(lL.x), pi2 = splat(lL.y), npi2 = splat(-lL.y);

    u64 z1 = splat(byx[h]), z2 = splat(byx[h + H2_]);
#pragma unroll
    for (int y = 0; y < NY_; ++y) {
        u64 yv = pk2(y0[b0 * NY_ + y], y0[(b0 + 1) * NY_ + y]);
        z1 = ffma2(splat(Wyx[h * NY_ + y]), yv, z1);
        z2 = ffma2(splat(Wyx[(h + H2_) * NY_ + y]), yv, z2);
    }
#pragma unroll 4
    for (int v = 0; v < NV_; ++v) {
        g_init[v][bp][h][0] = z1;
        g_init[v][bp][h][1] = z2;
        u64 f1 = g_final[v][bp][h][0];
        u64 f2 = g_final[v][bp][h][1];
        u64 n1 = ffma2(pr2, z1, ffma2(npi2, z2, f1));
        u64 n2 = ffma2(pr2, z2, ffma2(pi2,  z1, f2));
        z1 = n1; z2 = n2;
    }
}

// =====================================================================
// Kernel 3: re-scan (2 chains x 8 steps per chunk) + fused Y projection
// grid (NBP_, S_), 128 threads, dynamic shared
// shared (u64): Xs[CH_][XROW_] | WkT[NY_][NH_] | Us[CH_][NU_]
// chunk c: row r = ch*8 + i  <->  t_seg = ch*32 + c*8 + i
// Phase B (R9): warp tg -> rows tg*4..+3; lane k-strided by 32; butterfly
// =====================================================================
#define SM3_U64 (CH_ * XROW_ + NY_ * NH_ + CH_ * NU_)
#define SM3_BYTES (SM3_U64 * 8)

__global__ void __launch_bounds__(128, 4) k_main(
    const float* __restrict__ U,
    const float* __restrict__ Wxy, const float* __restrict__ bxy,
    float* __restrict__ Y)
{
    extern __shared__ __align__(16) u64 sm[];
    u64* Xs  = sm;                        // [CH_][XROW_], col k: 2h->x1, 2h+1->x2
    u64* WkT = sm + CH_ * XROW_;          // [NY_][NH_] transposed splats
    u64* Us  = WkT + NY_ * NH_;           // [CH_][NU_]

    const int tid = threadIdx.x;
    const int h   = tid;
    const int bp  = blockIdx.x;
    const int s   = blockIdx.y;
    const int b0  = bp << 1;

    // prepack W transposed: WkT[y][k] = splat(Wxy[y][colmap(k)])
#pragma unroll
    for (int i = 0; i < 16; ++i) {
        int idx = tid * 16 + i;          // 0..2047
        int y = idx >> 8, k = idx & 255;
        int hh = k >> 1;
        int col = (k & 1) ? (hh + H2_) : hh;
        WkT[y * NH_ + k] = splat(Wxy[y * NH_ + col]);
    }

    float2 lm = g_lam[h];
    u64 re2 = splat(lm.x), im2 = splat(lm.y), ni2 = splat(-lm.y);

    // 2 chain states
    u64 x1[2], x2[2];
#pragma unroll
    for (int ch = 0; ch < 2; ++ch) {
        const int v = s * 2 + ch;
        x1[ch] = g_init[v][bp][h][0];
        x2[ch] = g_init[v][bp][h][1];
    }

    // phase-B roles (R9)
    const int lane = tid & 31;
    const int tg   = tid >> 5;           // warp -> rows tg*4..tg*4+3
    const int t_local = lane >> 3;
    const int oy      = lane & 7;
    const u64 biasp = splat(bxy[oy]);

    const float* Ub = U + ((size_t)s * L_ * NB_ + b0) * NU_;

    for (int c = 0; c < NCH_; ++c) {
        __syncthreads();                 // prev-chunk Xs reads done before rewrite
        {   // stage U: row r -> t_seg = (r>>3)*32 + c*8 + (r&7)  (coalesced per t)
            int r = tid >> 3, u = tid & 7;
            int t_seg = (r >> 3) * LSEG_ + c * 8 + (r & 7);
            const float* p = Ub + (size_t)t_seg * (NB_ * NU_) + u;
            Us[r * NU_ + u] = pk2(p[0], p[NU_]);
        }
        __syncthreads();

        // reload B splats per chunk (dead during phase B -> lower live regs)
        u64 Bp1[NU_], Bp2[NU_];
        load_B_splats(h, Bp1, Bp2);

        // ---- phase A: 8 steps on each of 2 independent chains ----
#pragma unroll
        for (int i = 0; i < 8; ++i) {
#pragma unroll
            for (int ch = 0; ch < 2; ++ch) {
                const int r = ch * 8 + i;
                const ulonglong2* up = (const ulonglong2*)(Us + r * NU_);
                ulonglong2 ua = up[0], ub = up[1], uc = up[2], ud = up[3];
                u64 uu[8] = { ua.x, ua.y, ub.x, ub.y, uc.x, uc.y, ud.x, ud.y };
                u64 bu1 = fmul2(Bp1[0], uu[0]);
                u64 bu2 = fmul2(Bp2[0], uu[0]);
#pragma unroll
                for (int u = 1; u < NU_; ++u) {
                    bu1 = ffma2(Bp1[u], uu[u], bu1);
                    bu2 = ffma2(Bp2[u], uu[u], bu2);
                }
                u64 nx1 = ffma2(re2, x1[ch], ffma2(ni2, x2[ch], bu1));
                u64 nx2 = ffma2(re2, x2[ch], ffma2(im2, x1[ch], bu2));
                x1[ch] = nx1; x2[ch] = nx2;
                *((ulonglong2*)(Xs + (size_t)r * XROW_ + 2 * h)) =
                    make_ulonglong2(nx1, nx2);
            }
        }
        __syncthreads();

        // ---- phase B: Y GEMM (R9 mapping, unchanged) ----
        u64 acc[32];
#pragma unroll
        for (int v = 0; v < 32; ++v) acc[v] = 0ull;

        const u64* xb0 = Xs + (size_t)(tg * 4 + 0) * XROW_ + lane;
        const u64* xb1 = Xs + (size_t)(tg * 4 + 1) * XROW_ + lane;
        const u64* xb2 = Xs + (size_t)(tg * 4 + 2) * XROW_ + lane;
        const u64* xb3 = Xs + (size_t)(tg * 4 + 3) * XROW_ + lane;
        const u64* wb  = WkT + lane;

#pragma unroll
        for (int j = 0; j < 8; ++j) {
            const int ko = j * 32;
            u64 xv0 = xb0[ko], xv1 = xb1[ko], xv2 = xb2[ko], xv3 = xb3[ko];
            u64 w0 = wb[0 * NH_ + ko], w1 = wb[1 * NH_ + ko];
            u64 w2 = wb[2 * NH_ + ko], w3 = wb[3 * NH_ + ko];
            u64 w4 = wb[4 * NH_ + ko], w5 = wb[5 * NH_ + ko];
            u64 w6 = wb[6 * NH_ + ko], w7 = wb[7 * NH_ + ko];

            acc[ 0] = ffma2(w0, xv0, acc[ 0]); acc[ 1] = ffma2(w1, xv0, acc[ 1]);
            acc[ 2] = ffma2(w2, xv0, acc[ 2]); acc[ 3] = ffma2(w3, xv0, acc[ 3]);
            acc[ 4] = ffma2(w4, xv0, acc[ 4]); acc[ 5] = ffma2(w5, xv0, acc[ 5]);
            acc[ 6] = ffma2(w6, xv0, acc[ 6]); acc[ 7] = ffma2(w7, xv0, acc[ 7]);
            acc[ 8] = ffma2(w0, xv1, acc[ 8]); acc[ 9] = ffma2(w1, xv1, acc[ 9]);
            acc[10] = ffma2(w2, xv1, acc[10]); acc[11] = ffma2(w3, xv1, acc[11]);
            acc[12] = ffma2(w4, xv1, acc[12]); acc[13] = ffma2(w5, xv1, acc[13]);
            acc[14] = ffma2(w6, xv1, acc[14]); acc[15] = ffma2(w7, xv1, acc[15]);
            acc[16] = ffma2(w0, xv2, acc[16]); acc[17] = ffma2(w1, xv2, acc[17]);
            acc[18] = ffma2(w2, xv2, acc[18]); acc[19] = ffma2(w3, xv2, acc[19]);
            acc[20] = ffma2(w4, xv2, acc[20]); acc[21] = ffma2(w5, xv2, acc[21]);
            acc[22] = ffma2(w6, xv2, acc[22]); acc[23] = ffma2(w7, xv2, acc[23]);
            acc[24] = ffma2(w0, xv3, acc[24]); acc[25] = ffma2(w1, xv3, acc[25]);
            acc[26] = ffma2(w2, xv3, acc[26]); acc[27] = ffma2(w3, xv3, acc[27]);
            acc[28] = ffma2(w4, xv3, acc[28]); acc[29] = ffma2(w5, xv3, acc[29]);
            acc[30] = ffma2(w6, xv3, acc[30]); acc[31] = ffma2(w7, xv3, acc[31]);
        }

        // ---- butterfly allreduce over 32 lanes with value exchange ----
        {
            int n = 32;
#pragma unroll
            for (int d = 16; d >= 1; d >>= 1) {
                n >>= 1;
                const bool hi = (lane & d) != 0;
#pragma unroll
                for (int i = 0; i < 16; ++i) {
                    if (i < n) {
                        u64 snd = hi ? acc[i] : acc[i + n];
                        u64 rcv = __shfl_xor_sync(0xFFFFFFFFu, snd, d);
                        u64 kp  = hi ? acc[i + n] : acc[i];
                        acc[i] = fadd2(kp, rcv);
                    }
                }
            }
        }

        // lane owns row tg*4 + t_local; map row -> t_seg; store to Y
        {
            u64 r = fadd2(acc[0], biasp);
            float f0, f1; upk2(r, f0, f1);
            int row = tg * 4 + t_local;
            int t_seg = (row >> 3) * LSEG_ + c * 8 + (row & 7);
            int tgl = s * L_ + t_seg;
            float* yp = Y + ((size_t)tgl * NB_ + b0) * NY_ + oy;
            yp[0]   = f0;
            yp[NY_] = f1;
        }
    }
}

// =====================================================================
extern "C" void kernel_launch(void* const* d_in, const int* in_sizes, int n_in,
                              void* d_out, int out_size)
{
    const float* y0  = (const float*)d_in[0];
    const float* U   = (const float*)d_in[1];
    const float* lr  = (const float*)d_in[2];
    const float* li  = (const float*)d_in[3];
    const float* B   = (const float*)d_in[4];
    const float* mB  = (const float*)d_in[5];
    const float* Wyx = (const float*)d_in[6];
    const float* byx = (const float*)d_in[7];
    const float* Wxy = (const float*)d_in[8];
    const float* bxy = (const float*)d_in[9];
    float* Y = (float*)d_out;

    cudaFuncSetAttribute(k_main, cudaFuncAttributeMaxDynamicSharedMemorySize, SM3_BYTES);

    dim3 grid(NBP_, S_);
    k_pre <<<8, 16>>>(lr, li, B, mB);
    k_seg <<<grid, 128>>>(U);
    k_comb<<<NBP_, 128>>>(y0, Wyx, byx);
    k_main<<<grid, 128, SM3_BYTES>>>(U, Wxy, bxy, Y);
}

// round 15
// speedup vs baseline: 1.1627x; 1.0150x over previous
#include <cuda_runtime.h>
#include <math.h>

typedef unsigned long long u64;

#define T_    2048
#define NB_   64
#define NU_   8
#define NH_   256
#define H2_   128
#define NY_   8
#define S_    32           // segments (L_=64 each)
#define L_    64
#define NSQ_  6            // log2(L_)
#define NBP_  32           // NB_/2 (batch pairs)
#define CH_   16           // chunk of timesteps
#define NCH_  4            // L_/CH_
#define CHS_  16           // k_seg chunk
#define NCHS_ 4
#define XROW_ 256          // Xs row stride (u64)

// scratch (device globals; no allocation allowed)
__device__ u64 g_final[S_][NBP_][H2_][2];
__device__ u64 g_init [S_][NBP_][H2_][2];

// precomputed constants (k_pre)
__device__ float2 g_lam [H2_];     // lambda
__device__ float2 g_lam2[H2_];     // lambda^2
__device__ float2 g_lamL[H2_];     // lambda^L
__device__ float  g_B1[H2_][NU_];  // B[h]   * exp(mB[h])
__device__ float  g_B2[H2_][NU_];  // B[h+H2]* exp(mB[h+H2])
__device__ float  g_C1[H2_][NU_];  // re*B1 - im*B2
__device__ float  g_C2[H2_][NU_];  // im*B1 + re*B2
__device__ __align__(16) u64 g_B1p[H2_][NU_];
__device__ __align__(16) u64 g_B2p[H2_][NU_];

// ---- packed f32x2 helpers ----
static __device__ __forceinline__ u64 pk2(float lo, float hi) {
    u64 r; asm("mov.b64 %0, {%1,%2};" : "=l"(r) : "f"(lo), "f"(hi)); return r;
}
static __device__ __forceinline__ void upk2(u64 v, float& lo, float& hi) {
    asm("mov.b64 {%0,%1}, %2;" : "=f"(lo), "=f"(hi) : "l"(v));
}
static __device__ __forceinline__ u64 ffma2(u64 a, u64 b, u64 c) {
    u64 d; asm("fma.rn.f32x2 %0,%1,%2,%3;" : "=l"(d) : "l"(a), "l"(b), "l"(c)); return d;
}
static __device__ __forceinline__ u64 fmul2(u64 a, u64 b) {
    u64 d; asm("mul.rn.f32x2 %0,%1,%2;" : "=l"(d) : "l"(a), "l"(b)); return d;
}
static __device__ __forceinline__ u64 fadd2(u64 a, u64 b) {
    u64 d; asm("add.rn.f32x2 %0,%1,%2;" : "=l"(d) : "l"(a), "l"(b)); return d;
}
static __device__ __forceinline__ u64 splat(float v) { return pk2(v, v); }

static __device__ __forceinline__ void load_B_splats(int h, u64* Bp1, u64* Bp2) {
    const ulonglong2* p1 = (const ulonglong2*)g_B1p[h];
    const ulonglong2* p2 = (const ulonglong2*)g_B2p[h];
    ulonglong2 a0 = p1[0], a1 = p1[1], a2 = p1[2], a3 = p1[3];
    ulonglong2 c0 = p2[0], c1 = p2[1], c2 = p2[2], c3 = p2[3];
    Bp1[0]=a0.x; Bp1[1]=a0.y; Bp1[2]=a1.x; Bp1[3]=a1.y;
    Bp1[4]=a2.x; Bp1[5]=a2.y; Bp1[6]=a3.x; Bp1[7]=a3.y;
    Bp2[0]=c0.x; Bp2[1]=c0.y; Bp2[2]=c1.x; Bp2[3]=c1.y;
    Bp2[4]=c2.x; Bp2[5]=c2.y; Bp2[6]=c3.x; Bp2[7]=c3.y;
}

// =====================================================================
// Kernel 0: one-time constant precompute (all DP math lives here)
// =====================================================================
__global__ void k_pre(
    const float* __restrict__ lr, const float* __restrict__ li,
    const float* __restrict__ B, const float* __restrict__ mB)
{
    const int h = blockIdx.x * 16 + threadIdx.x;
    double e1 = exp((double)mB[h]);
    double e2 = exp((double)mB[h + H2_]);
    double r  = exp(-fabs((double)lr[h]));
    double th = 1.5707963267948966 * (double)li[h];
    double re = r * cos(th);
    double im = r * sin(th);
    g_lam[h]  = make_float2((float)re, (float)im);
    g_lam2[h] = make_float2((float)(re * re - im * im), (float)(2.0 * re * im));
    double pr = re, pi = im;
#pragma unroll
    for (int i = 0; i < NSQ_; ++i) {
        double nr = pr * pr - pi * pi;
        double ni = 2.0 * pr * pi;
        pr = nr; pi = ni;
    }
    g_lamL[h] = make_float2((float)pr, (float)pi);
#pragma unroll
    for (int u = 0; u < NU_; ++u) {
        double b1 = (double)B[h * NU_ + u] * e1;
        double b2 = (double)B[(h + H2_) * NU_ + u] * e2;
        float b1f = (float)b1, b2f = (float)b2;
        g_B1[h][u] = b1f;
        g_B2[h][u] = b2f;
        g_B1p[h][u] = pk2(b1f, b1f);
        g_B2p[h][u] = pk2(b2f, b2f);
        g_C1[h][u] = (float)(re * b1 - im * b2);
        g_C2[h][u] = (float)(im * b1 + re * b2);
    }
}

// =====================================================================
// Kernel 1: per-segment local scan (zero init, 2-step fused) -> g_final
// grid (NBP_, S_), 128 threads  (proven R9 form)
// =====================================================================
__global__ void __launch_bounds__(128, 4) k_seg(const float* __restrict__ U)
{
    const int h  = threadIdx.x;
    const int bp = blockIdx.x;
    const int s  = blockIdx.y;
    const int b0 = bp << 1;

    u64 B1s[NU_], B2s[NU_], C1s[NU_], C2s[NU_];
#pragma unroll
    for (int u = 0; u < NU_; ++u) {
        B1s[u] = splat(g_B1[h][u]);
        B2s[u] = splat(g_B2[h][u]);
        C1s[u] = splat(g_C1[h][u]);
        C2s[u] = splat(g_C2[h][u]);
    }
    float2 l2 = g_lam2[h];
    u64 R2 = splat(l2.x), I2 = splat(l2.y), nI2 = splat(-l2.y);

    u64 x1 = 0ull, x2 = 0ull;

    __shared__ __align__(16) u64 Us[CHS_][NU_];
    const float* Ub = U + ((size_t)s * L_ * NB_ + b0) * NU_;

    for (int c = 0; c < NCHS_; ++c) {
        __syncthreads();
        {
            int t = h >> 3, u = h & 7;
            const float* p = Ub + (size_t)(c * CHS_ + t) * (NB_ * NU_) + u;
            Us[t][u] = pk2(p[0], p[NU_]);
        }
        __syncthreads();
#pragma unroll
        for (int i = 0; i < CHS_ / 2; ++i) {
            const ulonglong2* pa = (const ulonglong2*)(&Us[2 * i][0]);
            ulonglong2 a0 = pa[0], a1 = pa[1], a2 = pa[2], a3 = pa[3];
            const ulonglong2* pb = (const ulonglong2*)(&Us[2 * i + 1][0]);
            ulonglong2 bq0 = pb[0], bq1 = pb[1], bq2 = pb[2], bq3 = pb[3];
            u64 uA[8] = { a0.x, a0.y, a1.x, a1.y, a2.x, a2.y, a3.x, a3.y };
            u64 uB[8] = { bq0.x, bq0.y, bq1.x, bq1.y, bq2.x, bq2.y, bq3.x, bq3.y };

            u64 p1 = fmul2(C1s[0], uA[0]);
            u64 q1 = fmul2(B1s[0], uB[0]);
            u64 p2 = fmul2(C2s[0], uA[0]);
            u64 q2 = fmul2(B2s[0], uB[0]);
#pragma unroll
            for (int u = 1; u < NU_; ++u) {
                p1 = ffma2(C1s[u], uA[u], p1);
                q1 = ffma2(B1s[u], uB[u], q1);
                p2 = ffma2(C2s[u], uA[u], p2);
                q2 = ffma2(B2s[u], uB[u], q2);
            }
            u64 acc1 = fadd2(p1, q1);
            u64 acc2 = fadd2(p2, q2);

            u64 nx1 = ffma2(R2, x1, ffma2(nI2, x2, acc1));
            u64 nx2 = ffma2(I2, x1, ffma2(R2, x2, acc2));
            x1 = nx1; x2 = nx2;
        }
    }
    g_final[s][bp][h][0] = x1;
    g_final[s][bp][h][1] = x2;
}

// =====================================================================
// Kernel 2: sequential combine across segments -> g_init
// grid (NBP_), 128 threads; g_final loads batched in waves of 8 (MLP)
// =====================================================================
__global__ void __launch_bounds__(128, 1) k_comb(
    const float* __restrict__ y0,
    const float* __restrict__ Wyx, const float* __restrict__ byx)
{
    const int h  = threadIdx.x;
    const int bp = blockIdx.x;
    const int b0 = bp << 1;

    float2 lL = g_lamL[h];
    u64 pr2 = splat(lL.x), pi2 = splat(lL.y), npi2 = splat(-lL.y);

    u64 z1 = splat(byx[h]), z2 = splat(byx[h + H2_]);
#pragma unroll
    for (int y = 0; y < NY_; ++y) {
        u64 yv = pk2(y0[b0 * NY_ + y], y0[(b0 + 1) * NY_ + y]);
        z1 = ffma2(splat(Wyx[h * NY_ + y]), yv, z1);
        z2 = ffma2(splat(Wyx[(h + H2_) * NY_ + y]), yv, z2);
    }
#pragma unroll
    for (int w = 0; w < S_ / 8; ++w) {
        // batch the 8 independent g_final loads (MLP=8 hides L2 latency)
        u64 f1a[8], f2a[8];
#pragma unroll
        for (int i = 0; i < 8; ++i) {
            ulonglong2 ff = *((const ulonglong2*)&g_final[w * 8 + i][bp][h][0]);
            f1a[i] = ff.x; f2a[i] = ff.y;
        }
#pragma unroll
        for (int i = 0; i < 8; ++i) {
            const int v = w * 8 + i;
            g_init[v][bp][h][0] = z1;
            g_init[v][bp][h][1] = z2;
            u64 n1 = ffma2(pr2, z1, ffma2(npi2, z2, f1a[i]));
            u64 n2 = ffma2(pr2, z2, ffma2(pi2,  z1, f2a[i]));
            z1 = n1; z2 = n2;
        }
    }
}

// =====================================================================
// Kernel 3: warp-specialized re-scan + fused Y projection
// grid (NBP_, S_), 256 threads:
//   warps 0-3 (tid<128): scan producer (one h each, batch-pair packed)
//   warps 4-7: GEMM consumer (R9 phase-B mapping)
// shared (u64): Xs[2][CH_][XROW_] double buffer | WkT[NY_][NH_]  (80KB)
// =====================================================================
#define SM3_U64 (2 * CH_ * XROW_ + NY_ * NH_)
#define SM3_BYTES (SM3_U64 * 8)

__global__ void __launch_bounds__(256, 2) k_main(
    const float* __restrict__ U,
    const float* __restrict__ Wxy, const float* __restrict__ bxy,
    float* __restrict__ Y)
{
    extern __shared__ __align__(16) u64 sm[];
    u64* XsA = sm;                         // buffer 0
    u64* XsB = sm + CH_ * XROW_;           // buffer 1
    u64* WkT = sm + 2 * CH_ * XROW_;       // [NY_][NH_] transposed splats

    const int tid = threadIdx.x;
    const int grp = tid >> 7;              // 0 = producer, 1 = consumer
    const int ht  = tid & 127;
    const int bp  = blockIdx.x;
    const int s   = blockIdx.y;
    const int b0  = bp << 1;

    // ---------------- producer state ----------------
    u64 x1 = 0, x2 = 0, re2 = 0, im2 = 0, ni2 = 0;
    u64 Bp1[NU_], Bp2[NU_];
    // ---------------- consumer state ----------------
    const int lane = ht & 31;
    const int tg   = ht >> 5;              // consumer warp -> rows tg*4..+3
    const int t_local = lane >> 3;
    const int oy      = lane & 7;
    u64 biasp = 0;

    if (grp == 1) {
        // consumer prologue: pack W transposed
#pragma unroll
        for (int i = 0; i < 16; ++i) {
            int idx = ht * 16 + i;         // 0..2047
            int y = idx >> 8, k = idx & 255;
            int hh = k >> 1;
            int col = (k & 1) ? (hh + H2_) : hh;
            WkT[y * NH_ + k] = splat(Wxy[y * NH_ + col]);
        }
        biasp = splat(bxy[oy]);
    } else {
        // producer prologue
        float2 lm = g_lam[ht];
        re2 = splat(lm.x); im2 = splat(lm.y); ni2 = splat(-lm.y);
        load_B_splats(ht, Bp1, Bp2);
        x1 = g_init[s][bp][ht][0];
        x2 = g_init[s][bp][ht][1];
    }

    const float4* U4 = (const float4*)(U + ((size_t)s * L_ * NB_ + b0) * NU_);
    // per timestep t: 16 consecutive floats (2 batches x 8 u) = 4 float4
    // at U4 + t*(NB_*NU_/4) + 0..3

    // producer fill of chunk c into buf
    auto fill = [&](int c, u64* buf) {
#pragma unroll
        for (int t = 0; t < CH_; ++t) {
            const int tt = c * CH_ + t;
            const float4* p = U4 + (size_t)tt * (NB_ * NU_ / 4);
            float4 a0 = p[0], a1 = p[1], c0 = p[2], c1 = p[3];
            u64 uu[8] = {
                pk2(a0.x, c0.x), pk2(a0.y, c0.y), pk2(a0.z, c0.z), pk2(a0.w, c0.w),
                pk2(a1.x, c1.x), pk2(a1.y, c1.y), pk2(a1.z, c1.z), pk2(a1.w, c1.w)
            };
            u64 bu1 = fmul2(Bp1[0], uu[0]);
            u64 bu2 = fmul2(Bp2[0], uu[0]);
#pragma unroll
            for (int u = 1; u < NU_; ++u) {
                bu1 = ffma2(Bp1[u], uu[u], bu1);
                bu2 = ffma2(Bp2[u], uu[u], bu2);
            }
            u64 nx1 = ffma2(re2, x1, ffma2(ni2, x2, bu1));
            u64 nx2 = ffma2(re2, x2, ffma2(im2, x1, bu2));
            x1 = nx1; x2 = nx2;
            *((ulonglong2*)(buf + (size_t)t * XROW_ + 2 * ht)) =
                make_ulonglong2(nx1, nx2);
        }
    };

    // consumer process of chunk c from buf
    auto process = [&](int c, const u64* buf) {
        u64 acc[32];
#pragma unroll
        for (int v = 0; v < 32; ++v) acc[v] = 0ull;

        const u64* xb0 = buf + (size_t)(tg * 4 + 0) * XROW_ + lane;
        const u64* xb1 = buf + (size_t)(tg * 4 + 1) * XROW_ + lane;
        const u64* xb2 = buf + (size_t)(tg * 4 + 2) * XROW_ + lane;
        const u64* xb3 = buf + (size_t)(tg * 4 + 3) * XROW_ + lane;
        const u64* wb  = WkT + lane;

#pragma unroll
        for (int j = 0; j < 8; ++j) {
            const int ko = j * 32;
            u64 xv0 = xb0[ko], xv1 = xb1[ko], xv2 = xb2[ko], xv3 = xb3[ko];
            u64 w0 = wb[0 * NH_ + ko], w1 = wb[1 * NH_ + ko];
            u64 w2 = wb[2 * NH_ + ko], w3 = wb[3 * NH_ + ko];
            u64 w4 = wb[4 * NH_ + ko], w5 = wb[5 * NH_ + ko];
            u64 w6 = wb[6 * NH_ + ko], w7 = wb[7 * NH_ + ko];

            acc[ 0] = ffma2(w0, xv0, acc[ 0]); acc[ 1] = ffma2(w1, xv0, acc[ 1]);
            acc[ 2] = ffma2(w2, xv0, acc[ 2]); acc[ 3] = ffma2(w3, xv0, acc[ 3]);
            acc[ 4] = ffma2(w4, xv0, acc[ 4]); acc[ 5] = ffma2(w5, xv0, acc[ 5]);
            acc[ 6] = ffma2(w6, xv0, acc[ 6]); acc[ 7] = ffma2(w7, xv0, acc[ 7]);
            acc[ 8] = ffma2(w0, xv1, acc[ 8]); acc[ 9] = ffma2(w1, xv1, acc[ 9]);
            acc[10] = ffma2(w2, xv1, acc[10]); acc[11] = ffma2(w3, xv1, acc[11]);
            acc[12] = ffma2(w4, xv1, acc[12]); acc[13] = ffma2(w5, xv1, acc[13]);
            acc[14] = ffma2(w6, xv1, acc[14]); acc[15] = ffma2(w7, xv1, acc[15]);
            acc[16] = ffma2(w0, xv2, acc[16]); acc[17] = ffma2(w1, xv2, acc[17]);
            acc[18] = ffma2(w2, xv2, acc[18]); acc[19] = ffma2(w3, xv2, acc[19]);
            acc[20] = ffma2(w4, xv2, acc[20]); acc[21] = ffma2(w5, xv2, acc[21]);
            acc[22] = ffma2(w6, xv2, acc[22]); acc[23] = ffma2(w7, xv2, acc[23]);
            acc[24] = ffma2(w0, xv3, acc[24]); acc[25] = ffma2(w1, xv3, acc[25]);
            acc[26] = ffma2(w2, xv3, acc[26]); acc[27] = ffma2(w3, xv3, acc[27]);
            acc[28] = ffma2(w4, xv3, acc[28]); acc[29] = ffma2(w5, xv3, acc[29]);
            acc[30] = ffma2(w6, xv3, acc[30]); acc[31] = ffma2(w7, xv3, acc[31]);
        }

        // butterfly allreduce over 32 lanes with value exchange
        {
            int n = 32;
#pragma unroll
            for (int d = 16; d >= 1; d >>= 1) {
                n >>= 1;
                const bool hi = (lane & d) != 0;
#pragma unroll
                for (int i = 0; i < 16; ++i) {
                    if (i < n) {
                        u64 snd = hi ? acc[i] : acc[i + n];
                        u64 rcv = __shfl_xor_sync(0xFFFFFFFFu, snd, d);
                        u64 kp  = hi ? acc[i + n] : acc[i];
                        acc[i] = fadd2(kp, rcv);
                    }
                }
            }
        }

        u64 r = fadd2(acc[0], biasp);
        float f0, f1; upk2(r, f0, f1);
        int tgl = s * L_ + c * CH_ + tg * 4 + t_local;
        float* yp = Y + ((size_t)tgl * NB_ + b0) * NY_ + oy;
        yp[0]   = f0;
        yp[NY_] = f1;
    };

    // ---- software pipeline: producer 1 chunk ahead ----
    if (grp == 0) fill(0, XsA);
    __syncthreads();
#pragma unroll
    for (int c = 0; c < NCH_; ++c) {
        u64* cur = (c & 1) ? XsB : XsA;
        u64* nxt = (c & 1) ? XsA : XsB;
        if (grp == 0) {
            if (c + 1 < NCH_) fill(c + 1, nxt);
        } else {
            process(c, cur);
        }
        __syncthreads();
    }
}

// =====================================================================
extern "C" void kernel_launch(void* const* d_in, const int* in_sizes, int n_in,
                              void* d_out, int out_size)
{
    const float* y0  = (const float*)d_in[0];
    const float* U   = (const float*)d_in[1];
    const float* lr  = (const float*)d_in[2];
    const float* li  = (const float*)d_in[3];
    const float* B   = (const float*)d_in[4];
    const float* mB  = (const float*)d_in[5];
    const float* Wyx = (const float*)d_in[6];
    const float* byx = (const float*)d_in[7];
    const float* Wxy = (const float*)d_in[8];
    const float* bxy = (const float*)d_in[9];
    float* Y = (float*)d_out;

    cudaFuncSetAttribute(k_main, cudaFuncAttributeMaxDynamicSharedMemorySize, SM3_BYTES);

    dim3 grid(NBP_, S_);
    k_pre <<<8, 16>>>(lr, li, B, mB);
    k_seg <<<grid, 128>>>(U);
    k_comb<<<NBP_, 128>>>(y0, Wyx, byx);
    k_main<<<grid, 256, SM3_BYTES>>>(U, Wxy, bxy, Y);
}

// round 16
// speedup vs baseline: 1.4526x; 1.2493x over previous
#include <cuda_runtime.h>
#include <math.h>

typedef unsigned long long u64;

#define T_    2048
#define NB_   64
#define NU_   8
#define NH_   256
#define H2_   128
#define NY_   8
#define S_    32
#define L_    64           // T_/S_
#define NSQ_  6            // log2(L_)
#define NBP_  32           // NB_/2 (batch pairs)
#define CH_   16           // chunk of timesteps
#define NCH_  4            // L_/CH_
#define XROW_ 258          // padded Xs row (in u64)

// scratch (device globals; no allocation allowed)
__device__ u64 g_final[S_][NBP_][H2_][2];
__device__ u64 g_init [S_][NBP_][H2_][2];

// precomputed constants (k_pre)
__device__ float2 g_lam [H2_];     // lambda
__device__ float2 g_lam2[H2_];     // lambda^2
__device__ float2 g_lamL[H2_];     // lambda^L
__device__ float  g_B1[H2_][NU_];  // B[h]   * exp(mB[h])
__device__ float  g_B2[H2_][NU_];  // B[h+H2]* exp(mB[h+H2])
__device__ float  g_C1[H2_][NU_];  // re*B1 - im*B2
__device__ float  g_C2[H2_][NU_];  // im*B1 + re*B2

// ---- packed f32x2 helpers (Blackwell FFMA2 path) ----
static __device__ __forceinline__ u64 pk2(float lo, float hi) {
    u64 r; asm("mov.b64 %0, {%1,%2};" : "=l"(r) : "f"(lo), "f"(hi)); return r;
}
static __device__ __forceinline__ void upk2(u64 v, float& lo, float& hi) {
    asm("mov.b64 {%0,%1}, %2;" : "=f"(lo), "=f"(hi) : "l"(v));
}
static __device__ __forceinline__ u64 ffma2(u64 a, u64 b, u64 c) {
    u64 d; asm("fma.rn.f32x2 %0,%1,%2,%3;" : "=l"(d) : "l"(a), "l"(b), "l"(c)); return d;
}
static __device__ __forceinline__ u64 fmul2(u64 a, u64 b) {
    u64 d; asm("mul.rn.f32x2 %0,%1,%2;" : "=l"(d) : "l"(a), "l"(b)); return d;
}
static __device__ __forceinline__ u64 fadd2(u64 a, u64 b) {
    u64 d; asm("add.rn.f32x2 %0,%1,%2;" : "=l"(d) : "l"(a), "l"(b)); return d;
}
static __device__ __forceinline__ u64 splat(float v) { return pk2(v, v); }

// =====================================================================
// Kernel 0: one-time constant precompute (all DP math lives here)
// grid 8 x 16 threads (spread DP across SMs)
// =====================================================================
__global__ void k_pre(
    const float* __restrict__ lr, const float* __restrict__ li,
    const float* __restrict__ B, const float* __restrict__ mB)
{
    const int h = blockIdx.x * 16 + threadIdx.x;
    double e1 = exp((double)mB[h]);
    double e2 = exp((double)mB[h + H2_]);
    double r  = exp(-fabs((double)lr[h]));
    double th = 1.5707963267948966 * (double)li[h];
    double re = r * cos(th);
    double im = r * sin(th);
    g_lam[h]  = make_float2((float)re, (float)im);
    g_lam2[h] = make_float2((float)(re * re - im * im), (float)(2.0 * re * im));
    double pr = re, pi = im;
#pragma unroll
    for (int i = 0; i < NSQ_; ++i) {
        double nr = pr * pr - pi * pi;
        double ni = 2.0 * pr * pi;
        pr = nr; pi = ni;
    }
    g_lamL[h] = make_float2((float)pr, (float)pi);
#pragma unroll
    for (int u = 0; u < NU_; ++u) {
        double b1 = (double)B[h * NU_ + u] * e1;
        double b2 = (double)B[(h + H2_) * NU_ + u] * e2;
        g_B1[h][u] = (float)b1;
        g_B2[h][u] = (float)b2;
        g_C1[h][u] = (float)(re * b1 - im * b2);
        g_C2[h][u] = (float)(im * b1 + re * b2);
    }
}

// =====================================================================
// Kernel 1: per-segment local scan (zero init, 2-step fused) -> g_final
// grid (NBP_, S_), 128 threads  (R9 proven form)
// =====================================================================
__global__ void __launch_bounds__(128, 4) k_seg(const float* __restrict__ U)
{
    const int h  = threadIdx.x;
    const int bp = blockIdx.x;
    const int s  = blockIdx.y;
    const int b0 = bp << 1;

    u64 B1s[NU_], B2s[NU_], C1s[NU_], C2s[NU_];
#pragma unroll
    for (int u = 0; u < NU_; ++u) {
        B1s[u] = splat(g_B1[h][u]);
        B2s[u] = splat(g_B2[h][u]);
        C1s[u] = splat(g_C1[h][u]);
        C2s[u] = splat(g_C2[h][u]);
    }
    float2 l2 = g_lam2[h];
    u64 R2 = splat(l2.x), I2 = splat(l2.y), nI2 = splat(-l2.y);

    u64 x1 = 0ull, x2 = 0ull;

    __shared__ __align__(16) u64 Us[CH_][NU_];
    const float* Ub = U + ((size_t)s * L_ * NB_ + b0) * NU_;

    for (int c = 0; c < NCH_; ++c) {
        __syncthreads();
        {   // stage CH_ steps of U, packed over the batch pair
            int t = h >> 3, u = h & 7;
            const float* p = Ub + (size_t)(c * CH_ + t) * (NB_ * NU_) + u;
            Us[t][u] = pk2(p[0], p[NU_]);
        }
        __syncthreads();
#pragma unroll
        for (int i = 0; i < CH_ / 2; ++i) {
            const ulonglong2* pa = (const ulonglong2*)(&Us[2 * i][0]);
            ulonglong2 a0 = pa[0], a1 = pa[1], a2 = pa[2], a3 = pa[3];
            const ulonglong2* pb = (const ulonglong2*)(&Us[2 * i + 1][0]);
            ulonglong2 bq0 = pb[0], bq1 = pb[1], bq2 = pb[2], bq3 = pb[3];
            u64 uA[8] = { a0.x, a0.y, a1.x, a1.y, a2.x, a2.y, a3.x, a3.y };
            u64 uB[8] = { bq0.x, bq0.y, bq1.x, bq1.y, bq2.x, bq2.y, bq3.x, bq3.y };

            u64 p1 = fmul2(C1s[0], uA[0]);
            u64 q1 = fmul2(B1s[0], uB[0]);
            u64 p2 = fmul2(C2s[0], uA[0]);
            u64 q2 = fmul2(B2s[0], uB[0]);
#pragma unroll
            for (int u = 1; u < NU_; ++u) {
                p1 = ffma2(C1s[u], uA[u], p1);
                q1 = ffma2(B1s[u], uB[u], q1);
                p2 = ffma2(C2s[u], uA[u], p2);
                q2 = ffma2(B2s[u], uB[u], q2);
            }
            u64 acc1 = fadd2(p1, q1);
            u64 acc2 = fadd2(p2, q2);

            u64 nx1 = ffma2(R2, x1, ffma2(nI2, x2, acc1));
            u64 nx2 = ffma2(I2, x1, ffma2(R2, x2, acc2));
            x1 = nx1; x2 = nx2;
        }
    }
    g_final[s][bp][h][0] = x1;
    g_final[s][bp][h][1] = x2;
}

// =====================================================================
// Kernel 2: sequential combine across segments -> g_init
// grid (NBP_), 128 threads; g_final loads batched in waves of 8 (MLP)
// =====================================================================
__global__ void __launch_bounds__(128, 1) k_comb(
    const float* __restrict__ y0,
    const float* __restrict__ Wyx, const float* __restrict__ byx)
{
    const int h  = threadIdx.x;
    const int bp = blockIdx.x;
    const int b0 = bp << 1;

    float2 lL = g_lamL[h];
    u64 pr2 = splat(lL.x), pi2 = splat(lL.y), npi2 = splat(-lL.y);

    u64 z1 = splat(byx[h]), z2 = splat(byx[h + H2_]);
#pragma unroll
    for (int y = 0; y < NY_; ++y) {
        u64 yv = pk2(y0[b0 * NY_ + y], y0[(b0 + 1) * NY_ + y]);
        z1 = ffma2(splat(Wyx[h * NY_ + y]), yv, z1);
        z2 = ffma2(splat(Wyx[(h + H2_) * NY_ + y]), yv, z2);
    }
#pragma unroll
    for (int w = 0; w < S_ / 8; ++w) {
        // batch the 8 independent g_final loads (MLP=8 hides L2 latency)
        u64 f1a[8], f2a[8];
#pragma unroll
        for (int i = 0; i < 8; ++i) {
            ulonglong2 ff = *((const ulonglong2*)&g_final[w * 8 + i][bp][h][0]);
            f1a[i] = ff.x; f2a[i] = ff.y;
        }
#pragma unroll
        for (int i = 0; i < 8; ++i) {
            const int v = w * 8 + i;
            g_init[v][bp][h][0] = z1;
            g_init[v][bp][h][1] = z2;
            u64 n1 = ffma2(pr2, z1, ffma2(npi2, z2, f1a[i]));
            u64 n2 = ffma2(pr2, z2, ffma2(pi2,  z1, f2a[i]));
            z1 = n1; z2 = n2;
        }
    }
}

// =====================================================================
// Kernel 3: re-scan with correct init + fused Y projection (R9 verbatim)
// grid (NBP_, S_), 128 threads, dynamic shared
// shared (u64): Xs[CH_][XROW_] | WkT[NY_][NH_] | Us[CH_][NU_]
// Phase B: thread = (warp tg -> 4 timesteps) x (lane kg -> k strided by 32)
//          warp butterfly allreduce -> direct store to Y (no Rd)
// =====================================================================
#define SM3_U64 (CH_ * XROW_ + NY_ * NH_ + CH_ * NU_)
#define SM3_BYTES (SM3_U64 * 8)

__global__ void __launch_bounds__(128, 4) k_main(
    const float* __restrict__ U,
    const float* __restrict__ Wxy, const float* __restrict__ bxy,
    float* __restrict__ Y)
{
    extern __shared__ __align__(16) u64 sm[];
    u64* Xs  = sm;                        // [CH_][XROW_], col k: 2h->x1, 2h+1->x2
    u64* WkT = sm + CH_ * XROW_;          // [NY_][NH_] transposed, interleaved cols
    u64* Us  = WkT + NY_ * NH_;           // [CH_][NU_]

    const int tid = threadIdx.x;
    const int h   = tid;
    const int bp  = blockIdx.x;
    const int s   = blockIdx.y;
    const int b0  = bp << 1;

    // prepack W transposed: WkT[y][k] = splat(Wxy[y][colmap(k)])
#pragma unroll
    for (int i = 0; i < 16; ++i) {
        int idx = tid * 16 + i;          // 0..2047
        int y = idx >> 8, k = idx & 255;
        int hh = k >> 1;
        int col = (k & 1) ? (hh + H2_) : hh;
        WkT[y * NH_ + k] = splat(Wxy[y * NH_ + col]);
    }

    u64 Bp1[NU_], Bp2[NU_];
#pragma unroll
    for (int u = 0; u < NU_; ++u) {
        Bp1[u] = splat(g_B1[h][u]);
        Bp2[u] = splat(g_B2[h][u]);
    }
    float2 lm = g_lam[h];
    u64 re2 = splat(lm.x), im2 = splat(lm.y), ni2 = splat(-lm.y);

    u64 x1 = g_init[s][bp][h][0];
    u64 x2 = g_init[s][bp][h][1];

    // phase-B roles
    const int lane = tid & 31;           // kg
    const int tg   = tid >> 5;           // warp -> 4 timesteps
    const int t_local = lane >> 3;       // output role after allreduce
    const int oy      = lane & 7;
    const u64 biasp = splat(bxy[oy]);

    const float* Ub = U + ((size_t)s * L_ * NB_ + b0) * NU_;

    for (int c = 0; c < NCH_; ++c) {
        __syncthreads();                 // Xs reads (prev chunk) done before rewrite
        {
            int t = tid >> 3, u = tid & 7;
            const float* p = Ub + (size_t)(c * CH_ + t) * (NB_ * NU_) + u;
            Us[t * NU_ + u] = pk2(p[0], p[NU_]);
        }
        __syncthreads();

        // ---- phase A: scan CH_ steps, stash states in shared ----
#pragma unroll
        for (int t = 0; t < CH_; ++t) {
            const ulonglong2* up = (const ulonglong2*)(Us + t * NU_);
            ulonglong2 ua = up[0], ub = up[1], uc = up[2], ud = up[3];
            u64 uu[8] = { ua.x, ua.y, ub.x, ub.y, uc.x, uc.y, ud.x, ud.y };
            u64 bu1 = fmul2(Bp1[0], uu[0]);
            u64 bu2 = fmul2(Bp2[0], uu[0]);
#pragma unroll
            for (int u = 1; u < NU_; ++u) {
                bu1 = ffma2(Bp1[u], uu[u], bu1);
                bu2 = ffma2(Bp2[u], uu[u], bu2);
            }
            u64 nx1 = ffma2(re2, x1, ffma2(ni2, x2, bu1));
            u64 nx2 = ffma2(re2, x2, ffma2(im2, x1, bu2));
            x1 = nx1; x2 = nx2;
            *((ulonglong2*)(Xs + (size_t)t * XROW_ + 2 * h)) = make_ulonglong2(x1, x2);
        }
        __syncthreads();

        // ---- phase B: Y GEMM, thread = (tg: 4 t) x (lane: k strided by 32) ----
        u64 acc[32];
#pragma unroll
        for (int v = 0; v < 32; ++v) acc[v] = 0ull;

        const u64* xb0 = Xs + (size_t)(tg * 4 + 0) * XROW_ + lane;
        const u64* xb1 = Xs + (size_t)(tg * 4 + 1) * XROW_ + lane;
        const u64* xb2 = Xs + (size_t)(tg * 4 + 2) * XROW_ + lane;
        const u64* xb3 = Xs + (size_t)(tg * 4 + 3) * XROW_ + lane;
        const u64* wb  = WkT + lane;

#pragma unroll
        for (int j = 0; j < 8; ++j) {
            const int ko = j * 32;
            u64 xv0 = xb0[ko], xv1 = xb1[ko], xv2 = xb2[ko], xv3 = xb3[ko];
            u64 w0 = wb[0 * NH_ + ko], w1 = wb[1 * NH_ + ko];
            u64 w2 = wb[2 * NH_ + ko], w3 = wb[3 * NH_ + ko];
            u64 w4 = wb[4 * NH_ + ko], w5 = wb[5 * NH_ + ko];
            u64 w6 = wb[6 * NH_ + ko], w7 = wb[7 * NH_ + ko];

            acc[ 0] = ffma2(w0, xv0, acc[ 0]); acc[ 1] = ffma2(w1, xv0, acc[ 1]);
            acc[ 2] = ffma2(w2, xv0, acc[ 2]); acc[ 3] = ffma2(w3, xv0, acc[ 3]);
            acc[ 4] = ffma2(w4, xv0, acc[ 4]); acc[ 5] = ffma2(w5, xv0, acc[ 5]);
            acc[ 6] = ffma2(w6, xv0, acc[ 6]); acc[ 7] = ffma2(w7, xv0, acc[ 7]);
            acc[ 8] = ffma2(w0, xv1, acc[ 8]); acc[ 9] = ffma2(w1, xv1, acc[ 9]);
            acc[10] = ffma2(w2, xv1, acc[10]); acc[11] = ffma2(w3, xv1, acc[11]);
            acc[12] = ffma2(w4, xv1, acc[12]); acc[13] = ffma2(w5, xv1, acc[13]);
            acc[14] = ffma2(w6, xv1, acc[14]); acc[15] = ffma2(w7, xv1, acc[15]);
            acc[16] = ffma2(w0, xv2, acc[16]); acc[17] = ffma2(w1, xv2, acc[17]);
            acc[18] = ffma2(w2, xv2, acc[18]); acc[19] = ffma2(w3, xv2, acc[19]);
            acc[20] = ffma2(w4, xv2, acc[20]); acc[21] = ffma2(w5, xv2, acc[21]);
            acc[22] = ffma2(w6, xv2, acc[22]); acc[23] = ffma2(w7, xv2, acc[23]);
            acc[24] = ffma2(w0, xv3, acc[24]); acc[25] = ffma2(w1, xv3, acc[25]);
            acc[26] = ffma2(w2, xv3, acc[26]); acc[27] = ffma2(w3, xv3, acc[27]);
            acc[28] = ffma2(w4, xv3, acc[28]); acc[29] = ffma2(w5, xv3, acc[29]);
            acc[30] = ffma2(w6, xv3, acc[30]); acc[31] = ffma2(w7, xv3, acc[31]);
        }

        // ---- butterfly allreduce over 32 lanes with value exchange ----
        {
            int n = 32;
#pragma unroll
            for (int d = 16; d >= 1; d >>= 1) {
                n >>= 1;
                const bool hi = (lane & d) != 0;
#pragma unroll
                for (int i = 0; i < 16; ++i) {
                    if (i < n) {
                        u64 snd = hi ? acc[i] : acc[i + n];
                        u64 rcv = __shfl_xor_sync(0xFFFFFFFFu, snd, d);
                        u64 kp  = hi ? acc[i + n] : acc[i];
                        acc[i] = fadd2(kp, rcv);
                    }
                }
            }
        }

        // lane owns (t_local, oy) fully reduced; add bias, store straight to Y
        {
            u64 r = fadd2(acc[0], biasp);
            float f0, f1; upk2(r, f0, f1);
            int tgl = s * L_ + c * CH_ + tg * 4 + t_local;
            float* yp = Y + ((size_t)tgl * NB_ + b0) * NY_ + oy;
            yp[0]   = f0;
            yp[NY_] = f1;
        }
    }
}

// =====================================================================
extern "C" void kernel_launch(void* const* d_in, const int* in_sizes, int n_in,
                              void* d_out, int out_size)
{
    const float* y0  = (const float*)d_in[0];
    const float* U   = (const float*)d_in[1];
    const float* lr  = (const float*)d_in[2];
    const float* li  = (const float*)d_in[3];
    const float* B   = (const float*)d_in[4];
    const float* mB  = (const float*)d_in[5];
    const float* Wyx = (const float*)d_in[6];
    const float* byx = (const float*)d_in[7];
    const float* Wxy = (const float*)d_in[8];
    const float* bxy = (const float*)d_in[9];
    float* Y = (float*)d_out;

    cudaFuncSetAttribute(k_main, cudaFuncAttributeMaxDynamicSharedMemorySize, SM3_BYTES);

    dim3 grid(NBP_, S_);
    k_pre <<<8, 16>>>(lr, li, B, mB);
    k_seg <<<grid, 128>>>(U);
    k_comb<<<NBP_, 128>>>(y0, Wyx, byx);
    k_main<<<grid, 128, SM3_BYTES>>>(U, Wxy, bxy, Y);
}

// round 17
// speedup vs baseline: 1.6304x; 1.1224x over previous
#include <cuda_runtime.h>
#include <math.h>

typedef unsigned long long u64;

#define T_    2048
#define NB_   64
#define NU_   8
#define NH_   256
#define H2_   128
#define NY_   8
#define S_    32
#define L_    64           // T_/S_
#define NSQ_  6            // log2(L_)
#define NBP_  32           // NB_/2 (batch pairs)
#define CH_   16           // chunk of timesteps
#define NCH_  4            // L_/CH_
#define XROW_ 258          // padded Xs row (in u64)

// scratch (device globals; no allocation allowed)
__device__ u64 g_final[S_][NBP_][H2_][2];
__device__ u64 g_init [S_][NBP_][H2_][2];

// precomputed constants (k_pre)
__device__ float2 g_lam [H2_];     // lambda
__device__ float2 g_lam2[H2_];     // lambda^2
__device__ float2 g_lamL[H2_];     // lambda^L
__device__ float  g_B1[H2_][NU_];  // B[h]   * exp(mB[h])
__device__ float  g_B2[H2_][NU_];  // B[h+H2]* exp(mB[h+H2])

// ---- packed f32x2 helpers (Blackwell FFMA2 path) ----
static __device__ __forceinline__ u64 pk2(float lo, float hi) {
    u64 r; asm("mov.b64 %0, {%1,%2};" : "=l"(r) : "f"(lo), "f"(hi)); return r;
}
static __device__ __forceinline__ void upk2(u64 v, float& lo, float& hi) {
    asm("mov.b64 {%0,%1}, %2;" : "=f"(lo), "=f"(hi) : "l"(v));
}
static __device__ __forceinline__ u64 ffma2(u64 a, u64 b, u64 c) {
    u64 d; asm("fma.rn.f32x2 %0,%1,%2,%3;" : "=l"(d) : "l"(a), "l"(b), "l"(c)); return d;
}
static __device__ __forceinline__ u64 fmul2(u64 a, u64 b) {
    u64 d; asm("mul.rn.f32x2 %0,%1,%2;" : "=l"(d) : "l"(a), "l"(b)); return d;
}
static __device__ __forceinline__ u64 fadd2(u64 a, u64 b) {
    u64 d; asm("add.rn.f32x2 %0,%1,%2;" : "=l"(d) : "l"(a), "l"(b)); return d;
}
static __device__ __forceinline__ u64 splat(float v) { return pk2(v, v); }

static __device__ __forceinline__ void load_B_splats(int h, u64* Bp1, u64* Bp2) {
#pragma unroll
    for (int u = 0; u < NU_; ++u) {
        Bp1[u] = splat(g_B1[h][u]);
        Bp2[u] = splat(g_B2[h][u]);
    }
}

// =====================================================================
// Kernel 0: one-time constant precompute (all DP math lives here)
// grid 8 x 16 threads (spread DP across SMs)
// =====================================================================
__global__ void k_pre(
    const float* __restrict__ lr, const float* __restrict__ li,
    const float* __restrict__ B, const float* __restrict__ mB)
{
    const int h = blockIdx.x * 16 + threadIdx.x;
    double e1 = exp((double)mB[h]);
    double e2 = exp((double)mB[h + H2_]);
    double r  = exp(-fabs((double)lr[h]));
    double th = 1.5707963267948966 * (double)li[h];
    double re = r * cos(th);
    double im = r * sin(th);
    g_lam[h]  = make_float2((float)re, (float)im);
    g_lam2[h] = make_float2((float)(re * re - im * im), (float)(2.0 * re * im));
    double pr = re, pi = im;
#pragma unroll
    for (int i = 0; i < NSQ_; ++i) {
        double nr = pr * pr - pi * pi;
        double ni = 2.0 * pr * pi;
        pr = nr; pi = ni;
    }
    g_lamL[h] = make_float2((float)pr, (float)pi);
#pragma unroll
    for (int u = 0; u < NU_; ++u) {
        g_B1[h][u] = (float)((double)B[h * NU_ + u] * e1);
        g_B2[h][u] = (float)((double)B[(h + H2_) * NU_ + u] * e2);
    }
}

// =====================================================================
// Kernel 1: per-segment local scan (zero init, 2-step fused) -> g_final
// grid (NBP_, S_), 128 threads.
// 2-step: x(t+2) = lam^2 x(t) + [lam*bu(t) + bu(t+1)]
// (combine computed dynamically -> no C matrices -> -32 regs -> 20 warps/SM)
// All 64 timesteps staged once (1 barrier).
// =====================================================================
__global__ void __launch_bounds__(128, 5) k_seg(const float* __restrict__ U)
{
    const int h  = threadIdx.x;
    const int bp = blockIdx.x;
    const int s  = blockIdx.y;
    const int b0 = bp << 1;

    u64 Bp1[NU_], Bp2[NU_];
    load_B_splats(h, Bp1, Bp2);
    float2 lm = g_lam[h];
    u64 re2 = splat(lm.x), im2 = splat(lm.y), ni2 = splat(-lm.y);
    float2 l2 = g_lam2[h];
    u64 R2 = splat(l2.x), I2 = splat(l2.y), nI2 = splat(-l2.y);

    // stage ALL 64 timesteps (4KB), coalesced
    __shared__ __align__(16) u64 Us[L_][NU_];
    const float* Ub = U + ((size_t)s * L_ * NB_ + b0) * NU_;
#pragma unroll
    for (int k = 0; k < 4; ++k) {
        int idx = k * 128 + h;
        int t = idx >> 3, u = idx & 7;
        const float* p = Ub + (size_t)t * (NB_ * NU_) + u;
        Us[t][u] = pk2(p[0], p[NU_]);
    }
    __syncthreads();

    u64 x1 = 0ull, x2 = 0ull;

#pragma unroll 4
    for (int i = 0; i < L_ / 2; ++i) {
        const ulonglong2* pa = (const ulonglong2*)(&Us[2 * i][0]);
        ulonglong2 a0 = pa[0], a1 = pa[1], a2 = pa[2], a3 = pa[3];
        const ulonglong2* pb = (const ulonglong2*)(&Us[2 * i + 1][0]);
        ulonglong2 bq0 = pb[0], bq1 = pb[1], bq2 = pb[2], bq3 = pb[3];
        u64 uA[8] = { a0.x, a0.y, a1.x, a1.y, a2.x, a2.y, a3.x, a3.y };
        u64 uB[8] = { bq0.x, bq0.y, bq1.x, bq1.y, bq2.x, bq2.y, bq3.x, bq3.y };

        // bu(t) and bu(t+1), two independent matvec trees each
        u64 pa1 = fmul2(Bp1[0], uA[0]);
        u64 pa2 = fmul2(Bp2[0], uA[0]);
        u64 pb1 = fmul2(Bp1[0], uB[0]);
        u64 pb2 = fmul2(Bp2[0], uB[0]);
#pragma unroll
        for (int u = 1; u < NU_; ++u) {
            pa1 = ffma2(Bp1[u], uA[u], pa1);
            pa2 = ffma2(Bp2[u], uA[u], pa2);
            pb1 = ffma2(Bp1[u], uB[u], pb1);
            pb2 = ffma2(Bp2[u], uB[u], pb2);
        }
        // g = lam * bu(t) + bu(t+1)
        u64 g1 = ffma2(re2, pa1, ffma2(ni2, pa2, pb1));
        u64 g2 = ffma2(im2, pa1, ffma2(re2, pa2, pb2));
        // x = lam^2 * x + g
        u64 nx1 = ffma2(R2, x1, ffma2(nI2, x2, g1));
        u64 nx2 = ffma2(I2, x1, ffma2(R2, x2, g2));
        x1 = nx1; x2 = nx2;
    }
    g_final[s][bp][h][0] = x1;
    g_final[s][bp][h][1] = x2;
}

// =====================================================================
// Kernel 2: sequential combine across segments -> g_init
// grid (NBP_), 128 threads; g_final loads batched in waves of 8 (MLP)
// =====================================================================
__global__ void __launch_bounds__(128, 1) k_comb(
    const float* __restrict__ y0,
    const float* __restrict__ Wyx, const float* __restrict__ byx)
{
    const int h  = threadIdx.x;
    const int bp = blockIdx.x;
    const int b0 = bp << 1;

    float2 lL = g_lamL[h];
    u64 pr2 = splat(lL.x), pi2 = splat(lL.y), npi2 = splat(-lL.y);

    u64 z1 = splat(byx[h]), z2 = splat(byx[h + H2_]);
#pragma unroll
    for (int y = 0; y < NY_; ++y) {
        u64 yv = pk2(y0[b0 * NY_ + y], y0[(b0 + 1) * NY_ + y]);
        z1 = ffma2(splat(Wyx[h * NY_ + y]), yv, z1);
        z2 = ffma2(splat(Wyx[(h + H2_) * NY_ + y]), yv, z2);
    }
#pragma unroll
    for (int w = 0; w < S_ / 8; ++w) {
        u64 f1a[8], f2a[8];
#pragma unroll
        for (int i = 0; i < 8; ++i) {
            ulonglong2 ff = *((const ulonglong2*)&g_final[w * 8 + i][bp][h][0]);
            f1a[i] = ff.x; f2a[i] = ff.y;
        }
#pragma unroll
        for (int i = 0; i < 8; ++i) {
            const int v = w * 8 + i;
            g_init[v][bp][h][0] = z1;
            g_init[v][bp][h][1] = z2;
            u64 n1 = ffma2(pr2, z1, ffma2(npi2, z2, f1a[i]));
            u64 n2 = ffma2(pr2, z2, ffma2(pi2,  z1, f2a[i]));
            z1 = n1; z2 = n2;
        }
    }
}

// =====================================================================
// Kernel 3: re-scan with correct init + fused Y projection
// grid (NBP_, S_), 128 threads, dynamic shared
// shared: Xs[CH_][XROW_] u64 | WkTf[NY_][NH_] f32 | Us[CH_][NU_] u64
// W stored as f32 (half the bytes/wavefronts), splat at use.
// Phase B: thread = (warp tg -> 4 timesteps) x (lane -> k strided by 32)
//          warp butterfly allreduce -> direct store to Y
// =====================================================================
#define WF_U64 (NY_ * NH_ / 2)     // 2048 f32 = 1024 u64-slots
#define SM3_U64 (CH_ * XROW_ + WF_U64 + CH_ * NU_)
#define SM3_BYTES (SM3_U64 * 8)

__global__ void __launch_bounds__(128, 4) k_main(
    const float* __restrict__ U,
    const float* __restrict__ Wxy, const float* __restrict__ bxy,
    float* __restrict__ Y)
{
    extern __shared__ __align__(16) u64 sm[];
    u64*   Xs   = sm;                          // [CH_][XROW_]
    float* WkTf = (float*)(sm + CH_ * XROW_);  // [NY_][NH_] f32, interleaved cols
    u64*   Us   = sm + CH_ * XROW_ + WF_U64;   // [CH_][NU_]

    const int tid = threadIdx.x;
    const int h   = tid;
    const int bp  = blockIdx.x;
    const int s   = blockIdx.y;
    const int b0  = bp << 1;

    // prepack W transposed as f32: WkTf[y][k] = Wxy[y][colmap(k)]
#pragma unroll
    for (int i = 0; i < 16; ++i) {
        int idx = tid * 16 + i;          // 0..2047
        int y = idx >> 8, k = idx & 255;
        int hh = k >> 1;
        int col = (k & 1) ? (hh + H2_) : hh;
        WkTf[y * NH_ + k] = Wxy[y * NH_ + col];
    }

    u64 Bp1[NU_], Bp2[NU_];
    load_B_splats(h, Bp1, Bp2);
    float2 lm = g_lam[h];
    u64 re2 = splat(lm.x), im2 = splat(lm.y), ni2 = splat(-lm.y);

    u64 x1 = g_init[s][bp][h][0];
    u64 x2 = g_init[s][bp][h][1];

    // phase-B roles
    const int lane = tid & 31;
    const int tg   = tid >> 5;           // warp -> 4 timesteps
    const int t_local = lane >> 3;
    const int oy      = lane & 7;
    const u64 biasp = splat(bxy[oy]);

    const float* Ub = U + ((size_t)s * L_ * NB_ + b0) * NU_;

    for (int c = 0; c < NCH_; ++c) {
        __syncthreads();                 // prev-chunk Xs reads done before rewrite
        {
            int t = tid >> 3, u = tid & 7;
            const float* p = Ub + (size_t)(c * CH_ + t) * (NB_ * NU_) + u;
            Us[t * NU_ + u] = pk2(p[0], p[NU_]);
        }
        __syncthreads();

        // ---- phase A: scan CH_ steps, stash states in shared ----
#pragma unroll
        for (int t = 0; t < CH_; ++t) {
            const ulonglong2* up = (const ulonglong2*)(Us + t * NU_);
            ulonglong2 ua = up[0], ub = up[1], uc = up[2], ud = up[3];
            u64 uu[8] = { ua.x, ua.y, ub.x, ub.y, uc.x, uc.y, ud.x, ud.y };
            u64 bu1 = fmul2(Bp1[0], uu[0]);
            u64 bu2 = fmul2(Bp2[0], uu[0]);
#pragma unroll
            for (int u = 1; u < NU_; ++u) {
                bu1 = ffma2(Bp1[u], uu[u], bu1);
                bu2 = ffma2(Bp2[u], uu[u], bu2);
            }
            u64 nx1 = ffma2(re2, x1, ffma2(ni2, x2, bu1));
            u64 nx2 = ffma2(re2, x2, ffma2(im2, x1, bu2));
            x1 = nx1; x2 = nx2;
            *((ulonglong2*)(Xs + (size_t)t * XROW_ + 2 * h)) = make_ulonglong2(x1, x2);
        }
        __syncthreads();

        // ---- phase B: Y GEMM, thread = (tg: 4 t) x (lane: k strided by 32) ----
        u64 acc[32];
#pragma unroll
        for (int v = 0; v < 32; ++v) acc[v] = 0ull;

        const u64*   xb0 = Xs + (size_t)(tg * 4 + 0) * XROW_ + lane;
        const u64*   xb1 = Xs + (size_t)(tg * 4 + 1) * XROW_ + lane;
        const u64*   xb2 = Xs + (size_t)(tg * 4 + 2) * XROW_ + lane;
        const u64*   xb3 = Xs + (size_t)(tg * 4 + 3) * XROW_ + lane;
        const float* wbf = WkTf + lane;

#pragma unroll
        for (int j = 0; j < 8; ++j) {
            const int ko = j * 32;
            u64 xv0 = xb0[ko], xv1 = xb1[ko], xv2 = xb2[ko], xv3 = xb3[ko];
            u64 w0 = splat(wbf[0 * NH_ + ko]);
            u64 w1 = splat(wbf[1 * NH_ + ko]);
            u64 w2 = splat(wbf[2 * NH_ + ko]);
            u64 w3 = splat(wbf[3 * NH_ + ko]);
            u64 w4 = splat(wbf[4 * NH_ + ko]);
            u64 w5 = splat(wbf[5 * NH_ + ko]);
            u64 w6 = splat(wbf[6 * NH_ + ko]);
            u64 w7 = splat(wbf[7 * NH_ + ko]);

            acc[ 0] = ffma2(w0, xv0, acc[ 0]); acc[ 1] = ffma2(w1, xv0, acc[ 1]);
            acc[ 2] = ffma2(w2, xv0, acc[ 2]); acc[ 3] = ffma2(w3, xv0, acc[ 3]);
            acc[ 4] = ffma2(w4, xv0, acc[ 4]); acc[ 5] = ffma2(w5, xv0, acc[ 5]);
            acc[ 6] = ffma2(w6, xv0, acc[ 6]); acc[ 7] = ffma2(w7, xv0, acc[ 7]);
            acc[ 8] = ffma2(w0, xv1, acc[ 8]); acc[ 9] = ffma2(w1, xv1, acc[ 9]);
            acc[10] = ffma2(w2, xv1, acc[10]); acc[11] = ffma2(w3, xv1, acc[11]);
            acc[12] = ffma2(w4, xv1, acc[12]); acc[13] = ffma2(w5, xv1, acc[13]);
            acc[14] = ffma2(w6, xv1, acc[14]); acc[15] = ffma2(w7, xv1, acc[15]);
            acc[16] = ffma2(w0, xv2, acc[16]); acc[17] = ffma2(w1, xv2, acc[17]);
            acc[18] = ffma2(w2, xv2, acc[18]); acc[19] = ffma2(w3, xv2, acc[19]);
            acc[20] = ffma2(w4, xv2, acc[20]); acc[21] = ffma2(w5, xv2, acc[21]);
            acc[22] = ffma2(w6, xv2, acc[22]); acc[23] = ffma2(w7, xv2, acc[23]);
            acc[24] = ffma2(w0, xv3, acc[24]); acc[25] = ffma2(w1, xv3, acc[25]);
            acc[26] = ffma2(w2, xv3, acc[26]); acc[27] = ffma2(w3, xv3, acc[27]);
            acc[28] = ffma2(w4, xv3, acc[28]); acc[29] = ffma2(w5, xv3, acc[29]);
            acc[30] = ffma2(w6, xv3, acc[30]); acc[31] = ffma2(w7, xv3, acc[31]);
        }

        // ---- butterfly allreduce over 32 lanes with value exchange ----
        {
            int n = 32;
#pragma unroll
            for (int d = 16; d >= 1; d >>= 1) {
                n >>= 1;
                const bool hi = (lane & d) != 0;
#pragma unroll
                for (int i = 0; i < 16; ++i) {
                    if (i < n) {
                        u64 snd = hi ? acc[i] : acc[i + n];
                        u64 rcv = __shfl_xor_sync(0xFFFFFFFFu, snd, d);
                        u64 kp  = hi ? acc[i + n] : acc[i];
                        acc[i] = fadd2(kp, rcv);
                    }
                }
            }
        }

        // lane owns (t_local, oy) fully reduced; add bias, store straight to Y
        {
            u64 r = fadd2(acc[0], biasp);
            float f0, f1; upk2(r, f0, f1);
            int tgl = s * L_ + c * CH_ + tg * 4 + t_local;
            float* yp = Y + ((size_t)tgl * NB_ + b0) * NY_ + oy;
            yp[0]   = f0;
            yp[NY_] = f1;
        }
    }
}

// =====================================================================
extern "C" void kernel_launch(void* const* d_in, const int* in_sizes, int n_in,
                              void* d_out, int out_size)
{
    const float* y0  = (const float*)d_in[0];
    const float* U   = (const float*)d_in[1];
    const float* lr  = (const float*)d_in[2];
    const float* li  = (const float*)d_in[3];
    const float* B   = (const float*)d_in[4];
    const float* mB  = (const float*)d_in[5];
    const float* Wyx = (const float*)d_in[6];
    const float* byx = (const float*)d_in[7];
    const float* Wxy = (const float*)d_in[8];
    const float* bxy = (const float*)d_in[9];
    float* Y = (float*)d_out;

    cudaFuncSetAttribute(k_main, cudaFuncAttributeMaxDynamicSharedMemorySize, SM3_BYTES);

    dim3 grid(NBP_, S_);
    k_pre <<<8, 16>>>(lr, li, B, mB);
    k_seg <<<grid, 128>>>(U);
    k_comb<<<NBP_, 128>>>(y0, Wyx, byx);
    k_main<<<grid, 128, SM3_BYTES>>>(U, Wxy, bxy, Y);
}